// round 9
// baseline (speedup 1.0000x reference)
#include <cuda_runtime.h>
#include <stdint.h>

#define NVIS 4096
#define NHID 1024
#define TT   64
#define BB   32

#define RM_OFF (NVIS*TT*BB)              /* 8388608  */
#define RT_OFF (RM_OFF + NHID*TT*BB)     /* 10485760 */

// ---------------------------------------------------------------------------
// Scratch (static device globals — no allocation)
// ---------------------------------------------------------------------------
__device__ __align__(16) uint32_t g_vbits[TT * NVIS];   // v bitmasks: word[t*NV+k], bit b
__device__ __align__(16) uint32_t g_vmbits[NVIS];       // vm bitmasks
__device__ __align__(16) uint32_t g_hbits[NHID];        // h bitmasks
__device__ __align__(16) float    g_rT[NHID * BB];      // r recurrence [h][b]
__device__ __align__(16) float    g_bias[NHID * BB];    // cached hid bias [h][b]

// ---------------------------------------------------------------------------
// Threefry-2x32 (exact; 20 rounds, 5 key injections) — DO NOT MODIFY (passing)
// ---------------------------------------------------------------------------
__host__ __device__ __forceinline__ void tf2x32(uint32_t k0, uint32_t k1,
                                                uint32_t x0, uint32_t x1,
                                                uint32_t& o0, uint32_t& o1) {
    uint32_t ks2 = k0 ^ k1 ^ 0x1BD11BDAu;
    x0 += k0; x1 += k1;
#define TF_R(r) { x0 += x1; x1 = (x1 << (r)) | (x1 >> (32 - (r))); x1 ^= x0; }
    TF_R(13) TF_R(15) TF_R(26) TF_R(6)   x0 += k1;  x1 += ks2 + 1u;
    TF_R(17) TF_R(29) TF_R(16) TF_R(24)  x0 += ks2; x1 += k0  + 2u;
    TF_R(13) TF_R(15) TF_R(26) TF_R(6)   x0 += k0;  x1 += k1  + 3u;
    TF_R(17) TF_R(29) TF_R(16) TF_R(24)  x0 += k1;  x1 += ks2 + 4u;
    TF_R(13) TF_R(15) TF_R(26) TF_R(6)   x0 += ks2; x1 += k0  + 5u;
#undef TF_R
    o0 = x0; o1 = x1;
}

__device__ __forceinline__ float jax_uniform(uint32_t k0, uint32_t k1, uint32_t idx) {
    uint32_t o0, o1;
    tf2x32(k0, k1, 0u, idx, o0, o1);
    uint32_t bits = o0 ^ o1;
    return __uint_as_float((bits >> 9) | 0x3f800000u) - 1.0f;
}

__device__ __forceinline__ float sigmoidf_(float x) {
    return 1.0f / (1.0f + expf(-x));
}

// Bit b of word as float 0.0f/1.0f (pure lat-4 ALU; no predicates, no I2F)
__device__ __forceinline__ float bitf(uint32_t word, int b) {
    uint32_t t = (word >> b) & 1u;
    return __uint_as_float(t * 0x3f800000u);
}

// ---------------------------------------------------------------------------
// Pack v [NV][T][B] -> bitmasks (once per replay)
// ---------------------------------------------------------------------------
__global__ void __launch_bounds__(256) pack_v_kernel(const float* __restrict__ v)
{
    int g    = blockIdx.x * 256 + threadIdx.x;
    int lane = g & 31;
    int w    = g >> 5;                 // 0 .. TT*NVIS-1
    int k    = w & (NVIS - 1);
    int t    = w >> 12;
    float val = v[(size_t)k * (TT * BB) + t * BB + lane];
    uint32_t m = __ballot_sync(0xffffffffu, val != 0.0f);
    if (lane == 0) g_vbits[t * NVIS + k] = m;
}

// ---------------------------------------------------------------------------
// Hidden kernel. Warp = 1 h row x 32 b (lane = b). Block = 4 warps = 4 h.
// Grid 256 -> 1024 warps (~1.7/SMSP). W/U rows: uniform LDG.128; v: bitmask.
// Strict ascending-k fmaf chain per output (bit-identical to passing kernel).
// phase 0: t=0 hid1; phase 1: t>0 hid1 (U@r bias); phase 2: hid2 (cached bias)
// ---------------------------------------------------------------------------
__global__ void __launch_bounds__(128) hid_kernel(
    const float* __restrict__ W,
    const float* __restrict__ U,
    const uint32_t* __restrict__ vbits,
    const float* __restrict__ bvec,
    int phase,
    float* __restrict__ r_out,   // rt column      (phase 0/1)
    float* __restrict__ s_out,   // r_model column (phase 2)
    uint32_t kk0, uint32_t kk1)
{
    const int b  = threadIdx.x & 31;
    const int h  = blockIdx.x * 4 + (threadIdx.x >> 5);   // 0..1023
    const int hb = h * BB + b;

    float bias;
    if (phase == 1) {
        // ---- U @ r (continuous r, ascending-k fmaf chain) ----
        float acc = 0.0f;
        const float4* U4 = reinterpret_cast<const float4*>(U + (size_t)h * NHID);
        const float*  rp = g_rT + b;
#pragma unroll 4
        for (int k4 = 0; k4 < NHID / 4; k4++) {
            float4 u4 = U4[k4];                       // uniform
            float r0 = rp[(4 * k4 + 0) * 32];         // coalesced
            float r1 = rp[(4 * k4 + 1) * 32];
            float r2 = rp[(4 * k4 + 2) * 32];
            float r3 = rp[(4 * k4 + 3) * 32];
            acc = fmaf(u4.x, r0, acc);
            acc = fmaf(u4.y, r1, acc);
            acc = fmaf(u4.z, r2, acc);
            acc = fmaf(u4.w, r3, acc);
        }
        bias = acc + bvec[h];
        g_bias[hb] = bias;
    } else if (phase == 0) {
        bias = bvec[h];
        g_bias[hb] = bias;
    } else {
        bias = g_bias[hb];
    }

    // ---- W @ v  (binary v via bitmask -> 0/1 float multiplier) ----
    float acc = 0.0f;
    const float4* W4 = reinterpret_cast<const float4*>(W + (size_t)h * NVIS);
    const uint4*  V4 = reinterpret_cast<const uint4*>(vbits);
#pragma unroll 4
    for (int k4 = 0; k4 < NVIS / 4; k4++) {
        float4 w4 = W4[k4];                           // uniform LDG.128
        uint4  m4 = V4[k4];                           // uniform LDG.128
        acc = fmaf(w4.x, bitf(m4.x, b), acc);
        acc = fmaf(w4.y, bitf(m4.y, b), acc);
        acc = fmaf(w4.z, bitf(m4.z, b), acc);
        acc = fmaf(w4.w, bitf(m4.w, b), acc);
    }

    float r = sigmoidf_(acc + bias);

    if (phase != 2) {
        r_out[(size_t)h * (TT * BB) + b] = r;
        g_rT[hb] = r;
    }
    float u = jax_uniform(kk0, kk1, (uint32_t)hb);
    int   p = (u < r);
    uint32_t m = __ballot_sync(0xffffffffu, p);
    if (b == 0) g_hbits[h] = m;
    if (phase == 2)
        s_out[(size_t)h * (TT * BB) + b] = p ? 1.0f : 0.0f;
}

// ---------------------------------------------------------------------------
// Visible kernel. Warp = 1 i-quad x 32 b (lane = b). Block = 4 warps = 16 i.
// Grid 256 -> 1024 warps. W[j][i0..i0+3]: uniform LDG.128 per j (warps of the
// same block hit the same 128B lines -> L1 reuse). h: bitmask, uniform uint4.
// Strict ascending-j fmaf chain per output.
// mode 0: vm -> g_vmbits (ballot) ; mode 1: v_model floats -> outp
// ---------------------------------------------------------------------------
__global__ void __launch_bounds__(128) vis_kernel(
    const float* __restrict__ W,
    const float* __restrict__ bv,
    int mode,
    float* __restrict__ outp,
    uint32_t kk0, uint32_t kk1)
{
    const int b  = threadIdx.x & 31;
    const int iq = blockIdx.x * 4 + (threadIdx.x >> 5);   // 0..1023
    const int i0 = iq * 4;

    float a0 = 0.f, a1 = 0.f, a2 = 0.f, a3 = 0.f;
    const float4* Wp = reinterpret_cast<const float4*>(W) + iq;  // W[j][i0..3]
    const uint4*  H4 = reinterpret_cast<const uint4*>(g_hbits);

#pragma unroll 2
    for (int j4 = 0; j4 < NHID / 4; j4++) {
        uint4 hm = H4[j4];                            // uniform
        float4 w;
        float f;
        w = Wp[(size_t)(4 * j4 + 0) * (NVIS / 4)];    // uniform LDG.128
        f = bitf(hm.x, b);
        a0 = fmaf(w.x, f, a0); a1 = fmaf(w.y, f, a1);
        a2 = fmaf(w.z, f, a2); a3 = fmaf(w.w, f, a3);
        w = Wp[(size_t)(4 * j4 + 1) * (NVIS / 4)];
        f = bitf(hm.y, b);
        a0 = fmaf(w.x, f, a0); a1 = fmaf(w.y, f, a1);
        a2 = fmaf(w.z, f, a2); a3 = fmaf(w.w, f, a3);
        w = Wp[(size_t)(4 * j4 + 2) * (NVIS / 4)];
        f = bitf(hm.z, b);
        a0 = fmaf(w.x, f, a0); a1 = fmaf(w.y, f, a1);
        a2 = fmaf(w.z, f, a2); a3 = fmaf(w.w, f, a3);
        w = Wp[(size_t)(4 * j4 + 3) * (NVIS / 4)];
        f = bitf(hm.w, b);
        a0 = fmaf(w.x, f, a0); a1 = fmaf(w.y, f, a1);
        a2 = fmaf(w.z, f, a2); a3 = fmaf(w.w, f, a3);
    }

    float accs[4] = {a0, a1, a2, a3};
#pragma unroll
    for (int q = 0; q < 4; q++) {
        float r = sigmoidf_(accs[q] + bv[i0 + q]);
        float u = jax_uniform(kk0, kk1, (uint32_t)((i0 + q) * BB + b));
        int pr = (u < r);
        uint32_t m = __ballot_sync(0xffffffffu, pr);
        if (mode == 0) {
            if (b == 0) g_vmbits[i0 + q] = m;
        } else {
            outp[(size_t)(i0 + q) * (TT * BB) + b] = pr ? 1.0f : 0.0f;
        }
    }
}

// ---------------------------------------------------------------------------
// Host: partitionable-threefry key schedule + launch sequence
// ---------------------------------------------------------------------------
extern "C" void kernel_launch(void* const* d_in, const int* in_sizes, int n_in,
                              void* d_out, int out_size)
{
    const float* v      = (const float*)d_in[0];   // [NV, T, B]
    const float* W      = (const float*)d_in[1];   // [NH, NV]
    const float* U      = (const float*)d_in[2];   // [NH, NH]
    const float* b_v    = (const float*)d_in[3];
    const float* b_h    = (const float*)d_in[4];
    const float* b_init = (const float*)d_in[5];
    float* out = (float*)d_out;

    // master key(42) = (0, 42); partitionable split: key_i = tf(key, 0, i)
    uint32_t k0a, k0b, ksa, ksb;
    tf2x32(0u, 42u, 0u, 0u, k0a, k0b);   // k0 (t=0 step key)
    tf2x32(0u, 42u, 0u, 1u, ksa, ksb);   // ks
    static uint32_t sub[TT][4][2];
    for (int t = 0; t < TT; t++) {
        uint32_t sk0, sk1;
        if (t == 0) { sk0 = k0a; sk1 = k0b; }
        else         tf2x32(ksa, ksb, 0u, (uint32_t)(t - 1), sk0, sk1);
        for (int i = 0; i < 4; i++)
            tf2x32(sk0, sk1, 0u, (uint32_t)i, sub[t][i][0], sub[t][i][1]);
    }

    void* p;
    cudaGetSymbolAddress(&p, g_vbits);  const uint32_t* pvb  = (const uint32_t*)p;
    cudaGetSymbolAddress(&p, g_vmbits); const uint32_t* pvmb = (const uint32_t*)p;

    pack_v_kernel<<<TT * NVIS * 32 / 256, 256>>>(v);

    for (int t = 0; t < TT; t++) {
        int ph1 = (t == 0) ? 0 : 1;
        // hid1: bias = (t==0 ? b_init : U@r + b_h); logit = W@v_t + bias
        hid_kernel<<<256, 128>>>(W, U, pvb + (size_t)t * NVIS,
                                 (t == 0) ? b_init : b_h, ph1,
                                 out + RT_OFF + (size_t)t * BB, nullptr,
                                 sub[t][0][0], sub[t][0][1]);
        // vis1: vm = bern(sigmoid(W.T h + b_v)) -> vm bitmasks
        vis_kernel<<<256, 128>>>(W, b_v, 0, nullptr,
                                 sub[t][1][0], sub[t][1][1]);
        // hid2: logit = W@vm + cached bias -> r_model sample
        hid_kernel<<<256, 128>>>(W, nullptr, pvmb, nullptr, 2,
                                 nullptr, out + RM_OFF + (size_t)t * BB,
                                 sub[t][2][0], sub[t][2][1]);
        // vis2: v_model = bern(sigmoid(W.T h + b_v)) -> output column
        vis_kernel<<<256, 128>>>(W, b_v, 1, out + (size_t)t * BB,
                                 sub[t][3][0], sub[t][3][1]);
    }
}

// round 11
// speedup vs baseline: 1.4169x; 1.4169x over previous
#include <cuda_runtime.h>
#include <stdint.h>

#define NVIS 4096
#define NHID 1024
#define TT   64
#define BB   32

#define RM_OFF (NVIS*TT*BB)              /* 8388608  */
#define RT_OFF (RM_OFF + NHID*TT*BB)     /* 10485760 */

// ---------------------------------------------------------------------------
// Scratch (static device globals — no allocation)
// ---------------------------------------------------------------------------
__device__ __align__(16) uint32_t g_vbits[TT * NVIS];   // v bitmasks: word[t*NV+k], bit b
__device__ __align__(16) uint32_t g_vmbits[NVIS];       // vm bitmasks
__device__ __align__(16) uint32_t g_hbits[NHID];        // h bitmasks
__device__ __align__(16) float    g_rT[NHID * BB];      // r recurrence [h][b]
__device__ __align__(16) float    g_bias[NHID * BB];    // cached hid bias [h][b]

// ---------------------------------------------------------------------------
// Threefry-2x32 (exact; 20 rounds, 5 key injections) — DO NOT MODIFY (passing)
// ---------------------------------------------------------------------------
__host__ __device__ __forceinline__ void tf2x32(uint32_t k0, uint32_t k1,
                                                uint32_t x0, uint32_t x1,
                                                uint32_t& o0, uint32_t& o1) {
    uint32_t ks2 = k0 ^ k1 ^ 0x1BD11BDAu;
    x0 += k0; x1 += k1;
#define TF_R(r) { x0 += x1; x1 = (x1 << (r)) | (x1 >> (32 - (r))); x1 ^= x0; }
    TF_R(13) TF_R(15) TF_R(26) TF_R(6)   x0 += k1;  x1 += ks2 + 1u;
    TF_R(17) TF_R(29) TF_R(16) TF_R(24)  x0 += ks2; x1 += k0  + 2u;
    TF_R(13) TF_R(15) TF_R(26) TF_R(6)   x0 += k0;  x1 += k1  + 3u;
    TF_R(17) TF_R(29) TF_R(16) TF_R(24)  x0 += k1;  x1 += ks2 + 4u;
    TF_R(13) TF_R(15) TF_R(26) TF_R(6)   x0 += ks2; x1 += k0  + 5u;
#undef TF_R
    o0 = x0; o1 = x1;
}

__device__ __forceinline__ float jax_uniform(uint32_t k0, uint32_t k1, uint32_t idx) {
    uint32_t o0, o1;
    tf2x32(k0, k1, 0u, idx, o0, o1);
    uint32_t bits = o0 ^ o1;
    return __uint_as_float((bits >> 9) | 0x3f800000u) - 1.0f;
}

__device__ __forceinline__ float sigmoidf_(float x) {
    return 1.0f / (1.0f + expf(-x));
}

// ---------------------------------------------------------------------------
// Masked adds (bit-identical to fmaf(w, v, acc), v in {0,1})
// ---------------------------------------------------------------------------
__device__ __forceinline__ void madd1(float& a0, float w0,
                                      uint32_t word, uint32_t bb) {
    asm("{\n\t.reg .pred p;\n\t.reg .b32 t;\n\t"
        "and.b32 t, %2, %3;\n\t"
        "setp.ne.u32 p, t, 0;\n\t"
        "@p add.f32 %0, %0, %1;\n\t}"
        : "+f"(a0) : "f"(w0), "r"(word), "r"(bb));
}
__device__ __forceinline__ void madd4(float& a0, float& a1, float& a2, float& a3,
                                      float4 w, uint32_t word, uint32_t bb) {
    asm("{\n\t.reg .pred p;\n\t.reg .b32 t;\n\t"
        "and.b32 t, %8, %9;\n\t"
        "setp.ne.u32 p, t, 0;\n\t"
        "@p add.f32 %0, %0, %4;\n\t"
        "@p add.f32 %1, %1, %5;\n\t"
        "@p add.f32 %2, %2, %6;\n\t"
        "@p add.f32 %3, %3, %7;\n\t}"
        : "+f"(a0), "+f"(a1), "+f"(a2), "+f"(a3)
        : "f"(w.x), "f"(w.y), "f"(w.z), "f"(w.w), "r"(word), "r"(bb));
}

// ---------------------------------------------------------------------------
// cp.async helpers
// ---------------------------------------------------------------------------
__device__ __forceinline__ uint32_t smem_u32(const void* p) {
    return (uint32_t)__cvta_generic_to_shared(p);
}
__device__ __forceinline__ void cp_async16(uint32_t saddr, const void* g) {
    asm volatile("cp.async.ca.shared.global [%0], [%1], 16;\n" :: "r"(saddr), "l"(g));
}
__device__ __forceinline__ void cp_commit() {
    asm volatile("cp.async.commit_group;\n");
}
__device__ __forceinline__ void cp_wait1() {
    asm volatile("cp.async.wait_group 1;\n" ::: "memory");
}
__device__ __forceinline__ void cp_wait0() {
    asm volatile("cp.async.wait_group 0;\n" ::: "memory");
}

// Stage one [4 rows x 512 cols] float tile (8KB) into smem. 128 threads.
__device__ __forceinline__ void stage4x512(uint32_t sbase, const float* gsrc,
                                           int rowstride, int tid) {
#pragma unroll
    for (int q = 0; q < 4; q++) {
        int cc  = q * 128 + tid;      // 0..511
        int rr  = cc >> 7;            // 0..3
        int c16 = cc & 127;           // 16B chunk within row
        cp_async16(sbase + (uint32_t)(rr * 512 + c16 * 4) * 4,
                   gsrc + (size_t)rr * rowstride + c16 * 4);
    }
    cp_commit();
}

// ---------------------------------------------------------------------------
// Pack v [NV][T][B] -> bitmasks (once per replay)
// ---------------------------------------------------------------------------
__global__ void __launch_bounds__(256) pack_v_kernel(const float* __restrict__ v)
{
    int g    = blockIdx.x * 256 + threadIdx.x;
    int lane = g & 31;
    int w    = g >> 5;                 // 0 .. TT*NVIS-1
    int k    = w & (NVIS - 1);
    int t    = w >> 12;
    float val = v[(size_t)k * (TT * BB) + t * BB + lane];
    uint32_t m = __ballot_sync(0xffffffffu, val != 0.0f);
    if (lane == 0) g_vbits[t * NVIS + k] = m;
}

// ---------------------------------------------------------------------------
// Hidden kernel. Warp = 1 h x 32 b (lane = b); block = 4 warps = 4 h.
// Grid 256 -> 1024 warps (~1.73/SMSP). W/U rows staged via cp.async (2-deep,
// 4 rows x 512 cols per tile); W read via LDS.128 broadcast; masks uniform LDG.
// Strict ascending-k chain per output (bit-identical to passing kernel).
// phase 0: t=0 hid1; phase 1: t>0 hid1 (U@r bias); phase 2: hid2 (cached bias)
// ---------------------------------------------------------------------------
__global__ void __launch_bounds__(128) hid_kernel(
    const float* __restrict__ W,
    const float* __restrict__ U,
    const uint32_t* __restrict__ vbits,
    const float* __restrict__ bvec,
    int phase,
    float* __restrict__ r_out,   // rt column      (phase 0/1)
    float* __restrict__ s_out,   // r_model column (phase 2)
    uint32_t kk0, uint32_t kk1)
{
    __shared__ float sW[2][4 * 512];   // 16KB double-buffered tile (4 rows)
    const int tid   = threadIdx.x;
    const int wid   = tid >> 5;
    const int b     = tid & 31;
    const int hbase = blockIdx.x * 4;
    const int h     = hbase + wid;     // 0..1023
    const int hb    = h * BB + b;
    const uint32_t bb  = 1u << b;
    const uint32_t sm0 = smem_u32(&sW[0][0]);
    const uint32_t sm1 = smem_u32(&sW[1][0]);

    float bias;
    if (phase == 1) {
        // ---- U @ r (continuous r, ascending-k fmaf chain) ----
        float acc = 0.0f;
        stage4x512(sm0, U + (size_t)hbase * NHID + 0,   NHID, tid);
        stage4x512(sm1, U + (size_t)hbase * NHID + 512, NHID, tid);
        for (int kt = 0; kt < 2; kt++) {
            if (kt == 0) cp_wait1(); else cp_wait0();
            __syncthreads();
            const float* wp = &sW[kt][wid * 512];
            const float* rp = g_rT + (size_t)(kt * 512) * 32 + b;
#pragma unroll 4
            for (int k = 0; k < 512; k += 4) {
                float4 u4 = *reinterpret_cast<const float4*>(wp + k);  // LDS.128 bcast
                float r0 = rp[(k + 0) * 32];
                float r1 = rp[(k + 1) * 32];
                float r2 = rp[(k + 2) * 32];
                float r3 = rp[(k + 3) * 32];
                acc = fmaf(u4.x, r0, acc);
                acc = fmaf(u4.y, r1, acc);
                acc = fmaf(u4.z, r2, acc);
                acc = fmaf(u4.w, r3, acc);
            }
            __syncthreads();
        }
        bias = acc + bvec[h];
        g_bias[hb] = bias;
    } else if (phase == 0) {
        bias = bvec[h];
        g_bias[hb] = bias;
    } else {
        bias = g_bias[hb];
    }

    // ---- W @ v  (binary v via bitmask, predicated adds) ----
    float acc = 0.0f;
    stage4x512(sm0, W + (size_t)hbase * NVIS + 0,   NVIS, tid);
    stage4x512(sm1, W + (size_t)hbase * NVIS + 512, NVIS, tid);
    for (int kt = 0; kt < 8; kt++) {
        if (kt < 7) cp_wait1(); else cp_wait0();
        __syncthreads();
        const float* wp = &sW[kt & 1][wid * 512];
        const uint4* vb = reinterpret_cast<const uint4*>(vbits + kt * 512);
#pragma unroll 4
        for (int k4 = 0; k4 < 128; k4++) {
            float4 w4 = *reinterpret_cast<const float4*>(wp + 4 * k4);  // LDS.128
            uint4  m4 = vb[k4];                                         // uniform LDG
            madd1(acc, w4.x, m4.x, bb);
            madd1(acc, w4.y, m4.y, bb);
            madd1(acc, w4.z, m4.z, bb);
            madd1(acc, w4.w, m4.w, bb);
        }
        __syncthreads();
        // tile kt+2 goes into the buffer just drained: parity kt&1
        if (kt + 2 < 8)
            stage4x512((kt & 1) ? sm1 : sm0,
                       W + (size_t)hbase * NVIS + (kt + 2) * 512, NVIS, tid);
    }

    float r = sigmoidf_(acc + bias);

    if (phase != 2) {
        r_out[(size_t)h * (TT * BB) + b] = r;
        g_rT[hb] = r;
    }
    float u = jax_uniform(kk0, kk1, (uint32_t)hb);
    int   p = (u < r);
    uint32_t m = __ballot_sync(0xffffffffu, p);
    if (b == 0) g_hbits[h] = m;
    if (phase == 2)
        s_out[(size_t)h * (TT * BB) + b] = p ? 1.0f : 0.0f;
}

// ---------------------------------------------------------------------------
// Visible kernel (unchanged from 12.36ms passing build).
// Thread = (4 i, b); warp = i-quad x 32 b; block = 16 i. Grid 256 x 128.
// W tiles [256 j x 16 i] via cp.async; h as bitmask. Ascending-j chain.
// mode 0: vm -> g_vmbits (ballot) ; mode 1: v_model floats -> outp
// ---------------------------------------------------------------------------
__global__ void __launch_bounds__(128) vis_kernel(
    const float* __restrict__ W,
    const float* __restrict__ bv,
    int mode,
    float* __restrict__ outp,
    uint32_t kk0, uint32_t kk1)
{
    __shared__ float sW[2][256 * 16];   // 32KB double-buffered
    const int tid   = threadIdx.x;
    const int wid   = tid >> 5;
    const int b     = tid & 31;
    const int ibase = blockIdx.x * 16;
    const int i0    = ibase + wid * 4;
    const uint32_t bb = 1u << b;
    const uint32_t sm0 = smem_u32(&sW[0][0]);
    const uint32_t sm1 = smem_u32(&sW[1][0]);

    auto stage = [&](uint32_t sbase, int jt) {
#pragma unroll
        for (int q = 0; q < 8; q++) {
            int cc  = q * 128 + tid;     // 0..1023
            int rr  = cc >> 2;           // 0..255
            int c16 = cc & 3;
            cp_async16(sbase + (uint32_t)(rr * 16 + c16 * 4) * 4,
                       W + (size_t)(jt * 256 + rr) * NVIS + ibase + c16 * 4);
        }
        cp_commit();
    };

    float a0 = 0.f, a1 = 0.f, a2 = 0.f, a3 = 0.f;
    stage(sm0, 0);
    stage(sm1, 1);
    for (int jt = 0; jt < 4; jt++) {
        if (jt < 3) cp_wait1(); else cp_wait0();
        __syncthreads();
        const float* wp = &sW[jt & 1][wid * 4];
        const uint32_t* hb = g_hbits + jt * 256;
#pragma unroll 4
        for (int j = 0; j < 256; j += 4) {
            uint4 hw = *reinterpret_cast<const uint4*>(hb + j);
            float4 w;
            w = *reinterpret_cast<const float4*>(wp + (j + 0) * 16);
            madd4(a0, a1, a2, a3, w, hw.x, bb);
            w = *reinterpret_cast<const float4*>(wp + (j + 1) * 16);
            madd4(a0, a1, a2, a3, w, hw.y, bb);
            w = *reinterpret_cast<const float4*>(wp + (j + 2) * 16);
            madd4(a0, a1, a2, a3, w, hw.z, bb);
            w = *reinterpret_cast<const float4*>(wp + (j + 3) * 16);
            madd4(a0, a1, a2, a3, w, hw.w, bb);
        }
        __syncthreads();
        if (jt + 2 < 4) stage((jt & 1) ? sm1 : sm0, jt + 2);
    }

    float accs[4] = {a0, a1, a2, a3};
#pragma unroll
    for (int q = 0; q < 4; q++) {
        float r = sigmoidf_(accs[q] + bv[i0 + q]);
        float u = jax_uniform(kk0, kk1, (uint32_t)((i0 + q) * BB + b));
        int pr = (u < r);
        uint32_t m = __ballot_sync(0xffffffffu, pr);
        if (mode == 0) {
            if (b == 0) g_vmbits[i0 + q] = m;
        } else {
            outp[(size_t)(i0 + q) * (TT * BB) + b] = pr ? 1.0f : 0.0f;
        }
    }
}

// ---------------------------------------------------------------------------
// Host: partitionable-threefry key schedule + launch sequence
// ---------------------------------------------------------------------------
extern "C" void kernel_launch(void* const* d_in, const int* in_sizes, int n_in,
                              void* d_out, int out_size)
{
    const float* v      = (const float*)d_in[0];   // [NV, T, B]
    const float* W      = (const float*)d_in[1];   // [NH, NV]
    const float* U      = (const float*)d_in[2];   // [NH, NH]
    const float* b_v    = (const float*)d_in[3];
    const float* b_h    = (const float*)d_in[4];
    const float* b_init = (const float*)d_in[5];
    float* out = (float*)d_out;

    // master key(42) = (0, 42); partitionable split: key_i = tf(key, 0, i)
    uint32_t k0a, k0b, ksa, ksb;
    tf2x32(0u, 42u, 0u, 0u, k0a, k0b);   // k0 (t=0 step key)
    tf2x32(0u, 42u, 0u, 1u, ksa, ksb);   // ks
    static uint32_t sub[TT][4][2];
    for (int t = 0; t < TT; t++) {
        uint32_t sk0, sk1;
        if (t == 0) { sk0 = k0a; sk1 = k0b; }
        else         tf2x32(ksa, ksb, 0u, (uint32_t)(t - 1), sk0, sk1);
        for (int i = 0; i < 4; i++)
            tf2x32(sk0, sk1, 0u, (uint32_t)i, sub[t][i][0], sub[t][i][1]);
    }

    void* p;
    cudaGetSymbolAddress(&p, g_vbits);  const uint32_t* pvb  = (const uint32_t*)p;
    cudaGetSymbolAddress(&p, g_vmbits); const uint32_t* pvmb = (const uint32_t*)p;

    pack_v_kernel<<<TT * NVIS * 32 / 256, 256>>>(v);

    for (int t = 0; t < TT; t++) {
        int ph1 = (t == 0) ? 0 : 1;
        // hid1: bias = (t==0 ? b_init : U@r + b_h); logit = W@v_t + bias
        hid_kernel<<<256, 128>>>(W, U, pvb + (size_t)t * NVIS,
                                 (t == 0) ? b_init : b_h, ph1,
                                 out + RT_OFF + (size_t)t * BB, nullptr,
                                 sub[t][0][0], sub[t][0][1]);
        // vis1: vm = bern(sigmoid(W.T h + b_v)) -> vm bitmasks
        vis_kernel<<<256, 128>>>(W, b_v, 0, nullptr,
                                 sub[t][1][0], sub[t][1][1]);
        // hid2: logit = W@vm + cached bias -> r_model sample
        hid_kernel<<<256, 128>>>(W, nullptr, pvmb, nullptr, 2,
                                 nullptr, out + RM_OFF + (size_t)t * BB,
                                 sub[t][2][0], sub[t][2][1]);
        // vis2: v_model = bern(sigmoid(W.T h + b_v)) -> output column
        vis_kernel<<<256, 128>>>(W, b_v, 1, out + (size_t)t * BB,
                                 sub[t][3][0], sub[t][3][1]);
    }
}

// round 12
// speedup vs baseline: 3.3559x; 2.3685x over previous
#include <cuda_runtime.h>
#include <stdint.h>

#define NVIS 4096
#define NHID 1024
#define TT   64
#define BB   32

#define RM_OFF (NVIS*TT*BB)              /* 8388608  */
#define RT_OFF (RM_OFF + NHID*TT*BB)     /* 10485760 */

// ---------------------------------------------------------------------------
// Scratch (static device globals — no allocation)
// ---------------------------------------------------------------------------
__device__ __align__(16) uint32_t g_vbits[TT * NVIS]; // v bitmasks word[t*NV+k], bit b
__device__ __align__(16) uint32_t g_vmbits[NVIS];     // vm bitmasks
__device__ __align__(16) uint32_t g_h1bits[NHID];     // hid1 samples (vis1 input)
__device__ __align__(16) uint32_t g_h2bits[NHID];     // hid2 samples (vis2 input)
__device__ __align__(16) float    g_rT[NHID * BB];    // r recurrence [h][b]
__device__ __align__(16) float    g_bias2[2][NHID*BB];// bias, double-buffered by t&1

// ---------------------------------------------------------------------------
// Threefry-2x32 (exact; 20 rounds, 5 key injections) — DO NOT MODIFY (passing)
// ---------------------------------------------------------------------------
__host__ __device__ __forceinline__ void tf2x32(uint32_t k0, uint32_t k1,
                                                uint32_t x0, uint32_t x1,
                                                uint32_t& o0, uint32_t& o1) {
    uint32_t ks2 = k0 ^ k1 ^ 0x1BD11BDAu;
    x0 += k0; x1 += k1;
#define TF_R(r) { x0 += x1; x1 = (x1 << (r)) | (x1 >> (32 - (r))); x1 ^= x0; }
    TF_R(13) TF_R(15) TF_R(26) TF_R(6)   x0 += k1;  x1 += ks2 + 1u;
    TF_R(17) TF_R(29) TF_R(16) TF_R(24)  x0 += ks2; x1 += k0  + 2u;
    TF_R(13) TF_R(15) TF_R(26) TF_R(6)   x0 += k0;  x1 += k1  + 3u;
    TF_R(17) TF_R(29) TF_R(16) TF_R(24)  x0 += k1;  x1 += ks2 + 4u;
    TF_R(13) TF_R(15) TF_R(26) TF_R(6)   x0 += ks2; x1 += k0  + 5u;
#undef TF_R
    o0 = x0; o1 = x1;
}

__device__ __forceinline__ float jax_uniform(uint32_t k0, uint32_t k1, uint32_t idx) {
    uint32_t o0, o1;
    tf2x32(k0, k1, 0u, idx, o0, o1);
    uint32_t bits = o0 ^ o1;
    return __uint_as_float((bits >> 9) | 0x3f800000u) - 1.0f;
}

__device__ __forceinline__ float sigmoidf_(float x) {
    return 1.0f / (1.0f + expf(-x));
}

// ---------------------------------------------------------------------------
// Masked adds (bit-identical to fmaf(w, v, acc), v in {0,1})
// ---------------------------------------------------------------------------
__device__ __forceinline__ void madd2(float& a0, float& a1, float w0, float w1,
                                      uint32_t word, uint32_t bb) {
    asm("{\n\t.reg .pred p;\n\t.reg .b32 t;\n\t"
        "and.b32 t, %4, %5;\n\t"
        "setp.ne.u32 p, t, 0;\n\t"
        "@p add.f32 %0, %0, %2;\n\t"
        "@p add.f32 %1, %1, %3;\n\t}"
        : "+f"(a0), "+f"(a1) : "f"(w0), "f"(w1), "r"(word), "r"(bb));
}
__device__ __forceinline__ void madd4(float& a0, float& a1, float& a2, float& a3,
                                      float4 w, uint32_t word, uint32_t bb) {
    asm("{\n\t.reg .pred p;\n\t.reg .b32 t;\n\t"
        "and.b32 t, %8, %9;\n\t"
        "setp.ne.u32 p, t, 0;\n\t"
        "@p add.f32 %0, %0, %4;\n\t"
        "@p add.f32 %1, %1, %5;\n\t"
        "@p add.f32 %2, %2, %6;\n\t"
        "@p add.f32 %3, %3, %7;\n\t}"
        : "+f"(a0), "+f"(a1), "+f"(a2), "+f"(a3)
        : "f"(w.x), "f"(w.y), "f"(w.z), "f"(w.w), "r"(word), "r"(bb));
}

// ---------------------------------------------------------------------------
// cp.async helpers
// ---------------------------------------------------------------------------
__device__ __forceinline__ uint32_t smem_u32(const void* p) {
    return (uint32_t)__cvta_generic_to_shared(p);
}
__device__ __forceinline__ void cp_async16(uint32_t saddr, const void* g) {
    asm volatile("cp.async.ca.shared.global [%0], [%1], 16;\n" :: "r"(saddr), "l"(g));
}
__device__ __forceinline__ void cp_commit() {
    asm volatile("cp.async.commit_group;\n");
}
__device__ __forceinline__ void cp_wait1() {
    asm volatile("cp.async.wait_group 1;\n" ::: "memory");
}
__device__ __forceinline__ void cp_wait0() {
    asm volatile("cp.async.wait_group 0;\n" ::: "memory");
}

// Stage one [8 rows x 512 cols] float tile (16KB) into smem. 128 threads.
__device__ __forceinline__ void stage8x512(uint32_t sbase, const float* gsrc,
                                           int rowstride, int tid) {
#pragma unroll
    for (int q = 0; q < 8; q++) {
        int cc  = q * 128 + tid;      // 0..1023
        int rr  = cc >> 7;            // 0..7
        int c16 = cc & 127;           // 16B chunk within row
        cp_async16(sbase + (uint32_t)(rr * 512 + c16 * 4) * 4,
                   gsrc + (size_t)rr * rowstride + c16 * 4);
    }
    cp_commit();
}

// ---------------------------------------------------------------------------
// Pack v [NV][T][B] -> bitmasks (once per replay)
// ---------------------------------------------------------------------------
__global__ void __launch_bounds__(256) pack_v_kernel(const float* __restrict__ v)
{
    int g    = blockIdx.x * 256 + threadIdx.x;
    int lane = g & 31;
    int w    = g >> 5;                 // 0 .. TT*NVIS-1
    int k    = w & (NVIS - 1);
    int t    = w >> 12;
    float val = v[(size_t)k * (TT * BB) + t * BB + lane];
    uint32_t m = __ballot_sync(0xffffffffu, val != 0.0f);
    if (lane == 0) g_vbits[t * NVIS + k] = m;
}

// ---------------------------------------------------------------------------
// Hidden body (exact 12.36ms-build inner loops, parameterized buffers).
// blk in [0,128): 8 h rows per block; thread = (2 h, b).
// phase 0: bias=bvec (b_init); phase 1: bias=seq(U@r)+bvec; phase 2: cached.
// ---------------------------------------------------------------------------
struct HidArgs {
    const float*    W;
    const float*    U;
    const uint32_t* vbits;
    const float*    bvec;
    int             phase;
    const float*    bias_rd;   // phase 2
    float*          bias_wr;   // phase 0/1
    float*          r_out;     // rt column (phase 0/1)
    float*          s_out;     // r_model column (phase 2)
    uint32_t*       hb_out;    // sample bitmask output
    uint32_t        kk0, kk1;
};

__device__ __forceinline__ void hid_body(int blk, const HidArgs a)
{
    __shared__ float sW[2][8 * 512];   // 32KB double-buffered tile
    const int tid   = threadIdx.x;
    const int wid   = tid >> 5;
    const int b     = tid & 31;
    const int hbase = blk * 8;
    const int h0    = hbase + wid * 2;
    const int h1    = h0 + 1;
    const uint32_t bb = 1u << b;
    const uint32_t sm0 = smem_u32(&sW[0][0]);
    const uint32_t sm1 = smem_u32(&sW[1][0]);

    float bias0, bias1;
    if (a.phase == 1) {
        // ---- U @ r (continuous r, ascending-k fmaf chain) ----
        float a0 = 0.f, a1 = 0.f;
        stage8x512(sm0, a.U + (size_t)hbase * NHID + 0,   NHID, tid);
        stage8x512(sm1, a.U + (size_t)hbase * NHID + 512, NHID, tid);
        for (int kt = 0; kt < 2; kt++) {
            if (kt == 0) cp_wait1(); else cp_wait0();
            __syncthreads();
            const float* w0p = &sW[kt][(wid * 2 + 0) * 512];
            const float* w1p = &sW[kt][(wid * 2 + 1) * 512];
            const float* rp  = g_rT + (size_t)(kt * 512) * 32 + b;
#pragma unroll 4
            for (int k = 0; k < 512; k += 4) {
                float4 w0 = *reinterpret_cast<const float4*>(w0p + k);
                float4 w1 = *reinterpret_cast<const float4*>(w1p + k);
                float r0 = rp[(k + 0) * 32];
                float r1 = rp[(k + 1) * 32];
                float r2 = rp[(k + 2) * 32];
                float r3 = rp[(k + 3) * 32];
                a0 = fmaf(w0.x, r0, a0); a1 = fmaf(w1.x, r0, a1);
                a0 = fmaf(w0.y, r1, a0); a1 = fmaf(w1.y, r1, a1);
                a0 = fmaf(w0.z, r2, a0); a1 = fmaf(w1.z, r2, a1);
                a0 = fmaf(w0.w, r3, a0); a1 = fmaf(w1.w, r3, a1);
            }
            __syncthreads();
        }
        bias0 = a0 + a.bvec[h0];
        bias1 = a1 + a.bvec[h1];
        a.bias_wr[h0 * 32 + b] = bias0;
        a.bias_wr[h1 * 32 + b] = bias1;
    } else if (a.phase == 0) {
        bias0 = a.bvec[h0];
        bias1 = a.bvec[h1];
        a.bias_wr[h0 * 32 + b] = bias0;
        a.bias_wr[h1 * 32 + b] = bias1;
    } else {
        bias0 = a.bias_rd[h0 * 32 + b];
        bias1 = a.bias_rd[h1 * 32 + b];
    }

    // ---- W @ v  (binary v via bitmask, predicated adds) ----
    float a0 = 0.f, a1 = 0.f;
    stage8x512(sm0, a.W + (size_t)hbase * NVIS + 0,   NVIS, tid);
    stage8x512(sm1, a.W + (size_t)hbase * NVIS + 512, NVIS, tid);
    for (int kt = 0; kt < 8; kt++) {
        if (kt < 7) cp_wait1(); else cp_wait0();
        __syncthreads();
        const float* w0p = &sW[kt & 1][(wid * 2 + 0) * 512];
        const float* w1p = &sW[kt & 1][(wid * 2 + 1) * 512];
        const uint32_t* vb = a.vbits + kt * 512;
#pragma unroll 4
        for (int k = 0; k < 512; k += 4) {
            uint4 vw = *reinterpret_cast<const uint4*>(vb + k);
            float4 w0 = *reinterpret_cast<const float4*>(w0p + k);
            float4 w1 = *reinterpret_cast<const float4*>(w1p + k);
            madd2(a0, a1, w0.x, w1.x, vw.x, bb);
            madd2(a0, a1, w0.y, w1.y, vw.y, bb);
            madd2(a0, a1, w0.z, w1.z, vw.z, bb);
            madd2(a0, a1, w0.w, w1.w, vw.w, bb);
        }
        __syncthreads();
        // tile kt+2 goes into the buffer just drained: parity kt&1
        if (kt + 2 < 8)
            stage8x512((kt & 1) ? sm1 : sm0,
                       a.W + (size_t)hbase * NVIS + (kt + 2) * 512, NVIS, tid);
    }

    float r0 = sigmoidf_(a0 + bias0);
    float r1 = sigmoidf_(a1 + bias1);

    if (a.phase != 2) {
        a.r_out[h0 * (TT * BB) + b] = r0;
        a.r_out[h1 * (TT * BB) + b] = r1;
        g_rT[h0 * 32 + b] = r0;
        g_rT[h1 * 32 + b] = r1;
    }
    float u0 = jax_uniform(a.kk0, a.kk1, (uint32_t)(h0 * BB + b));
    float u1 = jax_uniform(a.kk0, a.kk1, (uint32_t)(h1 * BB + b));
    int p0 = (u0 < r0), p1 = (u1 < r1);
    uint32_t m0 = __ballot_sync(0xffffffffu, p0);
    uint32_t m1 = __ballot_sync(0xffffffffu, p1);
    if (b == 0) { a.hb_out[h0] = m0; a.hb_out[h1] = m1; }
    if (a.phase == 2) {
        a.s_out[h0 * (TT * BB) + b] = p0 ? 1.0f : 0.0f;
        a.s_out[h1 * (TT * BB) + b] = p1 ? 1.0f : 0.0f;
    }
}

__global__ void __launch_bounds__(128) hid_single(HidArgs a)
{
    hid_body(blockIdx.x, a);
}

__global__ void __launch_bounds__(128) hid_fused(HidArgs a, HidArgs bgs)
{
    if (blockIdx.x < 128) hid_body(blockIdx.x, a);
    else                  hid_body(blockIdx.x - 128, bgs);
}

// ---------------------------------------------------------------------------
// Visible body (exact 12.36ms-build inner loops, parameterized buffers).
// blk in [0,256): 16 i per block; thread = (4 i, b).
// mode 0: vm -> vm_out (ballot) ; mode 1: v_model floats -> outp
// ---------------------------------------------------------------------------
struct VisArgs {
    const float*    W;
    const float*    bv;
    const uint32_t* hbits;
    int             mode;
    uint32_t*       vm_out;
    float*          outp;
    uint32_t        kk0, kk1;
};

__device__ __forceinline__ void vis_body(int blk, const VisArgs a)
{
    __shared__ float sW[2][256 * 16];   // 32KB double-buffered
    const int tid   = threadIdx.x;
    const int wid   = tid >> 5;
    const int b     = tid & 31;
    const int ibase = blk * 16;
    const int i0    = ibase + wid * 4;
    const uint32_t bb = 1u << b;
    const uint32_t sm0 = smem_u32(&sW[0][0]);
    const uint32_t sm1 = smem_u32(&sW[1][0]);

    auto stage = [&](uint32_t sbase, int jt) {
#pragma unroll
        for (int q = 0; q < 8; q++) {
            int cc  = q * 128 + tid;     // 0..1023
            int rr  = cc >> 2;           // 0..255
            int c16 = cc & 3;
            cp_async16(sbase + (uint32_t)(rr * 16 + c16 * 4) * 4,
                       a.W + (size_t)(jt * 256 + rr) * NVIS + ibase + c16 * 4);
        }
        cp_commit();
    };

    float a0 = 0.f, a1 = 0.f, a2 = 0.f, a3 = 0.f;
    stage(sm0, 0);
    stage(sm1, 1);
    for (int jt = 0; jt < 4; jt++) {
        if (jt < 3) cp_wait1(); else cp_wait0();
        __syncthreads();
        const float* wp = &sW[jt & 1][wid * 4];
        const uint32_t* hb = a.hbits + jt * 256;
#pragma unroll 4
        for (int j = 0; j < 256; j += 4) {
            uint4 hw = *reinterpret_cast<const uint4*>(hb + j);
            float4 w;
            w = *reinterpret_cast<const float4*>(wp + (j + 0) * 16);
            madd4(a0, a1, a2, a3, w, hw.x, bb);
            w = *reinterpret_cast<const float4*>(wp + (j + 1) * 16);
            madd4(a0, a1, a2, a3, w, hw.y, bb);
            w = *reinterpret_cast<const float4*>(wp + (j + 2) * 16);
            madd4(a0, a1, a2, a3, w, hw.z, bb);
            w = *reinterpret_cast<const float4*>(wp + (j + 3) * 16);
            madd4(a0, a1, a2, a3, w, hw.w, bb);
        }
        __syncthreads();
        if (jt + 2 < 4) stage((jt & 1) ? sm1 : sm0, jt + 2);
    }

    float accs[4] = {a0, a1, a2, a3};
#pragma unroll
    for (int q = 0; q < 4; q++) {
        float r = sigmoidf_(accs[q] + a.bv[i0 + q]);
        float u = jax_uniform(a.kk0, a.kk1, (uint32_t)((i0 + q) * BB + b));
        int pr = (u < r);
        uint32_t m = __ballot_sync(0xffffffffu, pr);
        if (a.mode == 0) {
            if (b == 0) a.vm_out[i0 + q] = m;
        } else {
            a.outp[(size_t)(i0 + q) * (TT * BB) + b] = pr ? 1.0f : 0.0f;
        }
    }
}

__global__ void __launch_bounds__(128) vis_single(VisArgs a)
{
    vis_body(blockIdx.x, a);
}

__global__ void __launch_bounds__(128) vis_fused(VisArgs a, VisArgs bgs)
{
    if (blockIdx.x < 256) vis_body(blockIdx.x, a);
    else                  vis_body(blockIdx.x - 256, bgs);
}

// ---------------------------------------------------------------------------
// Host: partitionable-threefry key schedule + pipelined launch sequence.
// Dependency DAG: hid1(t+1) independent of {vis1,hid2,vis2}(t); vis1(t+1)
// independent of vis2(t). Fuse the independent pairs into single launches.
// ---------------------------------------------------------------------------
extern "C" void kernel_launch(void* const* d_in, const int* in_sizes, int n_in,
                              void* d_out, int out_size)
{
    const float* v      = (const float*)d_in[0];   // [NV, T, B]
    const float* W      = (const float*)d_in[1];   // [NH, NV]
    const float* U      = (const float*)d_in[2];   // [NH, NH]
    const float* b_v    = (const float*)d_in[3];
    const float* b_h    = (const float*)d_in[4];
    const float* b_init = (const float*)d_in[5];
    float* out = (float*)d_out;

    // master key(42) = (0, 42); partitionable split: key_i = tf(key, 0, i)
    uint32_t k0a, k0b, ksa, ksb;
    tf2x32(0u, 42u, 0u, 0u, k0a, k0b);   // k0 (t=0 step key)
    tf2x32(0u, 42u, 0u, 1u, ksa, ksb);   // ks
    static uint32_t sub[TT][4][2];
    for (int t = 0; t < TT; t++) {
        uint32_t sk0, sk1;
        if (t == 0) { sk0 = k0a; sk1 = k0b; }
        else         tf2x32(ksa, ksb, 0u, (uint32_t)(t - 1), sk0, sk1);
        for (int i = 0; i < 4; i++)
            tf2x32(sk0, sk1, 0u, (uint32_t)i, sub[t][i][0], sub[t][i][1]);
    }

    void* p;
    cudaGetSymbolAddress(&p, g_vbits);  uint32_t* pvb  = (uint32_t*)p;
    cudaGetSymbolAddress(&p, g_vmbits); uint32_t* pvmb = (uint32_t*)p;
    cudaGetSymbolAddress(&p, g_h1bits); uint32_t* ph1  = (uint32_t*)p;
    cudaGetSymbolAddress(&p, g_h2bits); uint32_t* ph2  = (uint32_t*)p;
    cudaGetSymbolAddress(&p, g_bias2);  float*    pbias= (float*)p;
    float* bias_buf[2] = { pbias, pbias + NHID * BB };

    pack_v_kernel<<<TT * NVIS * 32 / 256, 256>>>(v);

    auto mk_hid1 = [&](int t) {
        HidArgs a;
        a.W = W; a.U = U;
        a.vbits = pvb + (size_t)t * NVIS;
        a.bvec  = (t == 0) ? b_init : b_h;
        a.phase = (t == 0) ? 0 : 1;
        a.bias_rd = nullptr;
        a.bias_wr = bias_buf[t & 1];
        a.r_out = out + RT_OFF + (size_t)t * BB;
        a.s_out = nullptr;
        a.hb_out = ph1;
        a.kk0 = sub[t][0][0]; a.kk1 = sub[t][0][1];
        return a;
    };
    auto mk_hid2 = [&](int t) {
        HidArgs a;
        a.W = W; a.U = nullptr;
        a.vbits = pvmb;
        a.bvec  = nullptr;
        a.phase = 2;
        a.bias_rd = bias_buf[t & 1];
        a.bias_wr = nullptr;
        a.r_out = nullptr;
        a.s_out = out + RM_OFF + (size_t)t * BB;
        a.hb_out = ph2;
        a.kk0 = sub[t][2][0]; a.kk1 = sub[t][2][1];
        return a;
    };
    auto mk_vis1 = [&](int t) {
        VisArgs a;
        a.W = W; a.bv = b_v; a.hbits = ph1;
        a.mode = 0; a.vm_out = pvmb; a.outp = nullptr;
        a.kk0 = sub[t][1][0]; a.kk1 = sub[t][1][1];
        return a;
    };
    auto mk_vis2 = [&](int t) {
        VisArgs a;
        a.W = W; a.bv = b_v; a.hbits = ph2;
        a.mode = 1; a.vm_out = nullptr; a.outp = out + (size_t)t * BB;
        a.kk0 = sub[t][3][0]; a.kk1 = sub[t][3][1];
        return a;
    };

    // Bootstrap: hid1(0), vis1(0)
    hid_single<<<128, 128>>>(mk_hid1(0));
    vis_single<<<256, 128>>>(mk_vis1(0));

    // Pipelined steady state
    for (int t = 0; t < TT - 1; t++) {
        // K3: hid1(t+1) [first 128 blocks, longer half] || hid2(t)
        hid_fused<<<256, 128>>>(mk_hid1(t + 1), mk_hid2(t));
        // K4: vis1(t+1) || vis2(t)
        vis_fused<<<512, 128>>>(mk_vis1(t + 1), mk_vis2(t));
    }

    // Tail: hid2(63), vis2(63)
    hid_single<<<128, 128>>>(mk_hid2(TT - 1));
    vis_single<<<256, 128>>>(mk_vis2(TT - 1));
}